// round 3
// baseline (speedup 1.0000x reference)
#include <cuda_runtime.h>
#include <cstdint>

#define B  8
#define L  30
#define D  512
#define NS 21
#define NI 8

// ---------------- scratch (device globals; no allocation) ----------------
__device__ float g_wc[B*L*NS];        // wc[b,l,s]
__device__ float g_aw[B*L];           // a_words[b,l]
__device__ float g_wsum[B*NS];        // weighted_c[b,s]
__device__ float g_aslots[B*NS];      // a_slots[b,s]
__device__ float g_aslots_sum[B];
__device__ float g_part[L*B*NS*D];    // partial u accumulators per l  (10.3 MB)
__device__ float g_uslots[B*NS*D];    // u_slots[b,s,k]
__device__ float g_wc2[B*NS*NI];      // wc2[b,s,i]
__device__ float g_wc2sum[B*NI];      // weighted_c2[b,i]
__device__ int   g_maxidx[B];
__device__ float g_part2[NS*B*D];     // partial intent accumulators per s

// ---------------- f32x2 packed-FMA helpers (sm_103a) ----------------
#define UNPACK2(a, b, i) asm("mov.b64 {%0, %1}, %2;" : "=f"(a), "=f"(b) : "l"(i))
#define FMA2(acc, a, b) asm("fma.rn.f32x2 %0, %1, %2, %3;" : "=l"(acc) : "l"(a), "l"(b), "l"(acc))

// ============ Kernel A: word->slot routing (logits, softmax, wc, slots) ============
__global__ void kA(const float* __restrict__ x, const float* __restrict__ wr,
                   float* __restrict__ out) {
    int b = blockIdx.x / L, l = blockIdx.x % L;
    __shared__ float xs[D];
    __shared__ float logits[NS];
    __shared__ float red[4];
    const float* xp = x + (size_t)(b*L + l)*D;
    int tid = threadIdx.x;              // 128 threads
    float psum = 0.f;
    for (int j = tid; j < D; j += 128) { float v = xp[j]; xs[j] = v; psum += v; }
    for (int o = 16; o; o >>= 1) psum += __shfl_xor_sync(~0u, psum, o);
    if ((tid & 31) == 0) red[tid >> 5] = psum;
    __syncthreads();
    float aw = (red[0] + red[1] + red[2] + red[3]) * (1.f / (float)D);
    int w = tid >> 5, lane = tid & 31;
    for (int n = w; n < NS; n += 4) {
        const float* wrow = wr + (size_t)(l*NS + n)*D;
        float acc = 0.f;
        for (int j = lane; j < D; j += 32) acc += wrow[j] * xs[j];
        for (int o = 16; o; o >>= 1) acc += __shfl_xor_sync(~0u, acc, o);
        if (lane == 0) logits[n] = acc;
    }
    __syncthreads();
    if (tid == 0) {
        float mx = logits[0]; int am = 0;
        for (int n = 1; n < NS; n++) if (logits[n] > mx) { mx = logits[n]; am = n; }
        float e[NS], se = 0.f;
        for (int n = 0; n < NS; n++) { e[n] = expf(logits[n] - mx); se += e[n]; }
        float inv = aw / se;
        for (int n = 0; n < NS; n++) g_wc[(b*L + l)*NS + n] = e[n] * inv;
        g_aw[b*L + l] = aw;
        out[b*L + l] = (float)am;   // slots (argmax of logits == argmax of softmax)
    }
}

// ============ Kernel B: per-batch slot statistics ============
__global__ void kB() {
    int b = blockIdx.x, lane = threadIdx.x;   // 32 threads
    float wsum = 0.f;
    if (lane < NS) for (int l = 0; l < L; l++) wsum += g_wc[(b*L + l)*NS + lane];
    float awp = 0.f;
    for (int l = lane; l < L; l += 32) awp += g_aw[b*L + l];
    for (int o = 16; o; o >>= 1) awp += __shfl_xor_sync(~0u, awp, o);
    float asl = (lane < NS) ? wsum / awp : 0.f;
    float ssum = asl;
    for (int o = 16; o; o >>= 1) ssum += __shfl_xor_sync(~0u, ssum, o);
    if (lane < NS) { g_wsum[b*NS + lane] = wsum; g_aslots[b*NS + lane] = asl; }
    if (lane == 0) g_aslots_sum[b] = ssum;
}

// ============ Kernel C: pose stream — the 660 MB weight read ============
// u_hat_slots[b,l,s,k] = sum_j W[l,s,k,j] * x[b,l,j]
// block = one (s,l); 256 thr, 2 CTA/SM. W and x consumed as raw ulonglong2
// (adjacent floats == f32x2 operand; zero pack instructions).
__global__ __launch_bounds__(256, 2) void kC(const float* __restrict__ x,
                                             const float* __restrict__ wp) {
    int blk = blockIdx.x;
    int s = blk / L, l = blk % L;
    __shared__ float4 xs4[B*(D/4)];          // x[b][j], 16 KB (bit-identical copy)
    __shared__ float  wcs[B];
    int tid = threadIdx.x;
    for (int i = tid; i < B*(D/4); i += 256) {
        int b = i >> 7, j4 = i & 127;
        xs4[i] = ((const float4*)(x + (size_t)(b*L + l)*D))[j4];
    }
    if (tid < B) wcs[tid] = g_wc[(tid*L + l)*NS + s];
    __syncthreads();
    int w = tid >> 5, lane = tid & 31;
    const float* Wp = wp + (size_t)(l*NS + s)*D*D;
    float* partp = g_part + (size_t)l*(B*NS*D);
    const ulonglong2* X = (const ulonglong2*)xs4;
    const int out_b = lane & 7, out_r = lane >> 3;
    float wcb = wcs[out_b];

    for (int rg = 0; rg < 16; rg++) {
        int k0 = (rg * 8 + w) * 4;           // rows [k0, k0+4)
        const ulonglong2* W0 = (const ulonglong2*)(Wp + (size_t)(k0 + 0)*D);
        const ulonglong2* W1 = (const ulonglong2*)(Wp + (size_t)(k0 + 1)*D);
        const ulonglong2* W2 = (const ulonglong2*)(Wp + (size_t)(k0 + 2)*D);
        const ulonglong2* W3 = (const ulonglong2*)(Wp + (size_t)(k0 + 3)*D);
        unsigned long long acc[4][8];
        #pragma unroll
        for (int r = 0; r < 4; r++)
            #pragma unroll
            for (int b = 0; b < 8; b++) acc[r][b] = 0ull;
        #pragma unroll
        for (int jj = 0; jj < 4; jj++) {
            int idx = (jj << 5) + lane;
            ulonglong2 w0 = W0[idx], w1 = W1[idx], w2 = W2[idx], w3 = W3[idx];
            #pragma unroll
            for (int b = 0; b < 8; b++) {
                ulonglong2 xv = X[(b << 7) + idx];
                FMA2(acc[0][b], w0.x, xv.x); FMA2(acc[0][b], w0.y, xv.y);
                FMA2(acc[1][b], w1.x, xv.x); FMA2(acc[1][b], w1.y, xv.y);
                FMA2(acc[2][b], w2.x, xv.x); FMA2(acc[2][b], w2.y, xv.y);
                FMA2(acc[3][b], w3.x, xv.x); FMA2(acc[3][b], w3.y, xv.y);
            }
        }
        // collapse f32x2 pairs -> 32 scalars (value index i = r*8+b)
        float v[32];
        #pragma unroll
        for (int r = 0; r < 4; r++)
            #pragma unroll
            for (int b = 0; b < 8; b++) {
                float lo, hi; UNPACK2(lo, hi, acc[r][b]);
                v[r*8 + b] = lo + hi;
            }
        // butterfly merge-transpose: 31 shuffles reduce all 32 values;
        // lane ends holding full sum of v[lane].
        int n = 32;
        #pragma unroll
        for (int o = 16; o; o >>= 1) {
            bool hi = (lane & o) != 0;
            n >>= 1;
            #pragma unroll
            for (int i = 0; i < 16; i++) {
                if (i < n) {
                    float send = hi ? v[i] : v[i + n];
                    float recv = __shfl_xor_sync(~0u, send, o);
                    v[i] = (hi ? v[i + n] : v[i]) + recv;
                }
            }
        }
        partp[((out_b*NS + s) << 9) + k0 + out_r] = v[0] * wcb;
    }
}

// ============ Kernel D: fixed-order reduce over l -> u_slots ============
__global__ void kD() {
    int t = blockIdx.x * 256 + threadIdx.x;       // [0, B*NS*D)
    float sum = 0.f;
    #pragma unroll
    for (int l = 0; l < L; l++) sum += g_part[(size_t)l*(B*NS*D) + t];
    int bs = t >> 9;
    g_uslots[t] = sum / g_wsum[bs];
}

// ============ Kernel E: slot->intent routing, a_intents, argmax dispatch ============
__global__ void kE(const float* __restrict__ wr_si) {
    int b = blockIdx.x, tid = threadIdx.x;        // 256 threads
    int w = tid >> 5, lane = tid & 31;
    __shared__ float lg[NS*NI];
    for (int d = w; d < NS*NI; d += 8) {
        int s = d / NI, i = d % NI;
        const float* wr = wr_si + (size_t)(s*NI + i)*D;
        const float* u = g_uslots + (size_t)(b*NS + s)*D;
        float acc = 0.f;
        for (int j = lane; j < D; j += 32) acc += wr[j] * u[j];
        for (int o = 16; o; o >>= 1) acc += __shfl_xor_sync(~0u, acc, o);
        if (lane == 0) lg[d] = acc;
    }
    __syncthreads();
    if (tid < 8) {
        int i = tid;
        float wcsum = 0.f;
        for (int s = 0; s < NS; s++) {
            float v = lg[s*NI + i];
            float m = v;
            for (int o = 4; o; o >>= 1) m = fmaxf(m, __shfl_xor_sync(0xff, m, o));
            float e = expf(v - m);
            float se = e;
            for (int o = 4; o; o >>= 1) se += __shfl_xor_sync(0xff, se, o);
            float wc2 = (e / se) * g_aslots[b*NS + s];
            g_wc2[(b*NS + s)*NI + i] = wc2;
            wcsum += wc2;
        }
        g_wc2sum[b*NI + i] = wcsum;
        lg[i] = wcsum / g_aslots_sum[b];          // a_intents
    }
    __syncthreads();
    if (tid == 0) {
        float mx = lg[0]; int am = 0;
        for (int i = 1; i < NI; i++) if (lg[i] > mx) { mx = lg[i]; am = i; }
        g_maxidx[b] = am;
    }
}

// ============ Kernel F: selected-intent COLUMN-SUM stream ============
// u_hat_intents[b,s,i,k] = (sum_j W[s,i,j,k]) * u_slots[b,s,k]
__global__ __launch_bounds__(512, 1) void kF(const float* __restrict__ wps) {
    int blk = blockIdx.x;
    int b = blk / NS, s = blk % NS;
    int ii = g_maxidx[b];
    int k = threadIdx.x;                           // 512 threads == D columns
    const float* Wp = wps + (size_t)(s*NI + ii)*D*D + k;
    float acc = 0.f;
    #pragma unroll 8
    for (int j = 0; j < D; j++) acc += Wp[(size_t)j*D];
    float u = g_uslots[(size_t)(b*NS + s)*D + k];
    float wc2s = g_wc2[(b*NS + s)*NI + ii];
    g_part2[(size_t)s*(B*D) + (b << 9) + k] = acc * u * wc2s;
}

// ============ Kernel G: fixed-order reduce over s + cls residual -> intents ============
__global__ void kG(const float* __restrict__ cls, float* __restrict__ out) {
    int t = blockIdx.x * 256 + threadIdx.x;       // [0, B*D)
    int b = t >> 9;
    float sum = 0.f;
    #pragma unroll
    for (int s = 0; s < NS; s++) sum += g_part2[(size_t)s*(B*D) + t];
    int ii = g_maxidx[b];
    out[B*L + t] = cls[t] + sum / g_wc2sum[b*NI + ii];
}

// ---------------- launch ----------------
extern "C" void kernel_launch(void* const* d_in, const int* in_sizes, int n_in,
                              void* d_out, int out_size) {
    const float* x     = (const float*)d_in[0];  // token_features (B,L,D)
    const float* cls   = (const float*)d_in[1];  // cls_token (B,D)
    const float* w_rws = (const float*)d_in[2];  // w_route_ws (L,NS,D)
    const float* w_pws = (const float*)d_in[3];  // w_pose_ws (L,NS,D,D)
    const float* w_rsi = (const float*)d_in[4];  // w_route_si (NS,NI,D)
    const float* w_psi = (const float*)d_in[5];  // w_pose_si (NS,NI,D,D)
    float* out = (float*)d_out;

    kA<<<B*L, 128>>>(x, w_rws, out);
    kB<<<B, 32>>>();
    kC<<<NS*L, 256>>>(x, w_pws);
    kD<<<(B*NS*D)/256, 256>>>();
    kE<<<B, 256>>>(w_rsi);
    kF<<<B*NS, 512>>>(w_psi);
    kG<<<(B*D)/256, 256>>>(cls, out);
}

// round 5
// speedup vs baseline: 1.2777x; 1.2777x over previous
#include <cuda_runtime.h>
#include <cstdint>

#define B  8
#define L  30
#define D  512
#define NS 21
#define NI 8

// ---------------- scratch (device globals; no allocation) ----------------
__device__ float g_wc[B*L*NS];        // wc[b,l,s]
__device__ float g_aw[B*L];           // a_words[b,l]
__device__ float g_wsum[B*NS];        // weighted_c[b,s]
__device__ float g_aslots[B*NS];      // a_slots[b,s]
__device__ float g_aslots_sum[B];
__device__ float g_part[L*B*NS*D];    // partial u accumulators per l  (10.3 MB)
__device__ float g_uslots[B*NS*D];    // u_slots[b,s,k]
__device__ float g_wc2[B*NS*NI];      // wc2[b,s,i]
__device__ float g_wc2sum[B*NI];      // weighted_c2[b,i]
__device__ int   g_maxidx[B];
__device__ float g_part2[NS*B*D];     // partial intent accumulators per s

// ---------------- f32x2 packed-FMA helpers (sm_103a) ----------------
#define UNPACK2(a, b, i) asm("mov.b64 {%0, %1}, %2;" : "=f"(a), "=f"(b) : "l"(i))
#define FMA2(acc, a, b) asm("fma.rn.f32x2 %0, %1, %2, %3;" : "=l"(acc) : "l"(a), "l"(b), "l"(acc))

// ============ Kernel A: word->slot routing (logits, softmax, wc, slots) ============
__global__ void kA(const float* __restrict__ x, const float* __restrict__ wr,
                   float* __restrict__ out) {
    int b = blockIdx.x / L, l = blockIdx.x % L;
    __shared__ float xs[D];
    __shared__ float logits[NS];
    __shared__ float red[4];
    const float* xp = x + (size_t)(b*L + l)*D;
    int tid = threadIdx.x;              // 128 threads
    float psum = 0.f;
    for (int j = tid; j < D; j += 128) { float v = xp[j]; xs[j] = v; psum += v; }
    for (int o = 16; o; o >>= 1) psum += __shfl_xor_sync(~0u, psum, o);
    if ((tid & 31) == 0) red[tid >> 5] = psum;
    __syncthreads();
    float aw = (red[0] + red[1] + red[2] + red[3]) * (1.f / (float)D);
    int w = tid >> 5, lane = tid & 31;
    for (int n = w; n < NS; n += 4) {
        const float* wrow = wr + (size_t)(l*NS + n)*D;
        float acc = 0.f;
        for (int j = lane; j < D; j += 32) acc += wrow[j] * xs[j];
        for (int o = 16; o; o >>= 1) acc += __shfl_xor_sync(~0u, acc, o);
        if (lane == 0) logits[n] = acc;
    }
    __syncthreads();
    if (tid == 0) {
        float mx = logits[0]; int am = 0;
        for (int n = 1; n < NS; n++) if (logits[n] > mx) { mx = logits[n]; am = n; }
        float e[NS], se = 0.f;
        for (int n = 0; n < NS; n++) { e[n] = expf(logits[n] - mx); se += e[n]; }
        float inv = aw / se;
        for (int n = 0; n < NS; n++) g_wc[(b*L + l)*NS + n] = e[n] * inv;
        g_aw[b*L + l] = aw;
        out[b*L + l] = (float)am;   // slots (argmax of logits == argmax of softmax)
    }
}

// ============ Kernel B: per-batch slot statistics (idempotent) ============
__global__ void kB() {
    int b = blockIdx.x, lane = threadIdx.x;   // 32 threads
    float wsum = 0.f;
    if (lane < NS) for (int l = 0; l < L; l++) wsum += g_wc[(b*L + l)*NS + lane];
    float awp = 0.f;
    for (int l = lane; l < L; l += 32) awp += g_aw[b*L + l];
    for (int o = 16; o; o >>= 1) awp += __shfl_xor_sync(~0u, awp, o);
    float asl = (lane < NS) ? wsum / awp : 0.f;
    float ssum = asl;
    for (int o = 16; o; o >>= 1) ssum += __shfl_xor_sync(~0u, ssum, o);
    if (lane < NS) { g_wsum[b*NS + lane] = wsum; g_aslots[b*NS + lane] = asl; }
    if (lane == 0) g_aslots_sum[b] = ssum;
}

// ============ Kernel C: pose stream — the 660 MB weight read (R2-proven core) ============
// u_hat_slots[b,l,s,k] = sum_j W[l,s,k,j] * x[b,l,j]
// block = one (s,l) pair; 512 threads, 16 warps; warp owns 32 rows (8 rgs x 4).
__global__ __launch_bounds__(512, 1) void kC(const float* __restrict__ x,
                                             const float* __restrict__ wp) {
    int blk = blockIdx.x;
    int s = blk / L, l = blk % L;
    __shared__ float4 xs4[B*(D/4)];          // x[b][j], 16 KB (bit-identical copy)
    __shared__ float  wcs[B];
    int tid = threadIdx.x;
    for (int i = tid; i < B*(D/4); i += 512) {
        int b = i >> 7, j4 = i & 127;
        xs4[i] = ((const float4*)(x + (size_t)(b*L + l)*D))[j4];
    }
    if (tid < B) wcs[tid] = g_wc[(tid*L + l)*NS + s];
    __syncthreads();
    int w = tid >> 5, lane = tid & 31;
    const float* Wp = wp + (size_t)(l*NS + s)*D*D;
    float* partp = g_part + (size_t)l*(B*NS*D);
    const ulonglong2* X = (const ulonglong2*)xs4;
    const int out_b = lane & 7, out_r = lane >> 3;
    float wcb = wcs[out_b];

    for (int rg = 0; rg < 8; rg++) {
        int k0 = (w << 5) + (rg << 2);       // rows [k0, k0+4)
        const ulonglong2* W0 = (const ulonglong2*)(Wp + (size_t)(k0 + 0)*D);
        const ulonglong2* W1 = (const ulonglong2*)(Wp + (size_t)(k0 + 1)*D);
        const ulonglong2* W2 = (const ulonglong2*)(Wp + (size_t)(k0 + 2)*D);
        const ulonglong2* W3 = (const ulonglong2*)(Wp + (size_t)(k0 + 3)*D);
        unsigned long long acc[4][8];
        #pragma unroll
        for (int r = 0; r < 4; r++)
            #pragma unroll
            for (int b = 0; b < 8; b++) acc[r][b] = 0ull;
        #pragma unroll
        for (int jj = 0; jj < 4; jj++) {
            int idx = (jj << 5) + lane;
            ulonglong2 w0 = W0[idx], w1 = W1[idx], w2 = W2[idx], w3 = W3[idx];
            #pragma unroll
            for (int b = 0; b < 8; b++) {
                ulonglong2 xv = X[(b << 7) + idx];
                FMA2(acc[0][b], w0.x, xv.x); FMA2(acc[0][b], w0.y, xv.y);
                FMA2(acc[1][b], w1.x, xv.x); FMA2(acc[1][b], w1.y, xv.y);
                FMA2(acc[2][b], w2.x, xv.x); FMA2(acc[2][b], w2.y, xv.y);
                FMA2(acc[3][b], w3.x, xv.x); FMA2(acc[3][b], w3.y, xv.y);
            }
        }
        // predicated full-reduce per value (R2-proven): lane (out_r,out_b) keeps its own
        float myv = 0.f;
        #pragma unroll
        for (int r = 0; r < 4; r++)
            #pragma unroll
            for (int b = 0; b < 8; b++) {
                float lo, hi; UNPACK2(lo, hi, acc[r][b]);
                float v = lo + hi;
                for (int o = 16; o; o >>= 1) v += __shfl_xor_sync(~0u, v, o);
                if (out_r == r && out_b == b) myv = v;
            }
        partp[((out_b*NS + s) << 9) + k0 + out_r] = myv * wcb;
    }
}

// ============ Kernel D: fixed-order reduce over l -> u_slots ============
__global__ void kD() {
    int t = blockIdx.x * 256 + threadIdx.x;       // [0, B*NS*D)
    float sum = 0.f;
    #pragma unroll
    for (int l = 0; l < L; l++) sum += g_part[(size_t)l*(B*NS*D) + t];
    int bs = t >> 9;
    g_uslots[t] = sum / g_wsum[bs];
}

// ============ Kernel E: slot->intent routing, a_intents, argmax dispatch ============
__global__ void kE(const float* __restrict__ wr_si) {
    int b = blockIdx.x, tid = threadIdx.x;        // 256 threads
    int w = tid >> 5, lane = tid & 31;
    __shared__ float lg[NS*NI];
    for (int d = w; d < NS*NI; d += 8) {
        int s = d / NI, i = d % NI;
        const float* wr = wr_si + (size_t)(s*NI + i)*D;
        const float* u = g_uslots + (size_t)(b*NS + s)*D;
        float acc = 0.f;
        for (int j = lane; j < D; j += 32) acc += wr[j] * u[j];
        for (int o = 16; o; o >>= 1) acc += __shfl_xor_sync(~0u, acc, o);
        if (lane == 0) lg[d] = acc;
    }
    __syncthreads();
    if (tid < 8) {
        int i = tid;
        float wcsum = 0.f;
        for (int s = 0; s < NS; s++) {
            float v = lg[s*NI + i];
            float m = v;
            for (int o = 4; o; o >>= 1) m = fmaxf(m, __shfl_xor_sync(0xff, m, o));
            float e = expf(v - m);
            float se = e;
            for (int o = 4; o; o >>= 1) se += __shfl_xor_sync(0xff, se, o);
            float wc2 = (e / se) * g_aslots[b*NS + s];
            g_wc2[(b*NS + s)*NI + i] = wc2;
            wcsum += wc2;
        }
        g_wc2sum[b*NI + i] = wcsum;
        lg[i] = wcsum / g_aslots_sum[b];          // a_intents
    }
    __syncthreads();
    if (tid == 0) {
        float mx = lg[0]; int am = 0;
        for (int i = 1; i < NI; i++) if (lg[i] > mx) { mx = lg[i]; am = i; }
        g_maxidx[b] = am;
    }
}

// ============ Kernel F: selected-intent COLUMN-SUM stream ============
// u_hat_intents[b,s,i,k] = (sum_j W[s,i,j,k]) * u_slots[b,s,k]
__global__ __launch_bounds__(512, 1) void kF(const float* __restrict__ wps) {
    int blk = blockIdx.x;
    int b = blk / NS, s = blk % NS;
    int ii = g_maxidx[b];
    int k = threadIdx.x;                           // 512 threads == D columns
    const float* Wp = wps + (size_t)(s*NI + ii)*D*D + k;
    float acc = 0.f;
    #pragma unroll 16
    for (int j = 0; j < D; j++) acc += Wp[(size_t)j*D];
    float u = g_uslots[(size_t)(b*NS + s)*D + k];
    float wc2s = g_wc2[(b*NS + s)*NI + ii];
    g_part2[(size_t)s*(B*D) + (b << 9) + k] = acc * u * wc2s;
}

// ============ Kernel G: fixed-order reduce over s + cls residual -> intents ============
__global__ void kG(const float* __restrict__ cls, float* __restrict__ out) {
    int t = blockIdx.x * 256 + threadIdx.x;       // [0, B*D)
    int b = t >> 9;
    float sum = 0.f;
    #pragma unroll
    for (int s = 0; s < NS; s++) sum += g_part2[(size_t)s*(B*D) + t];
    int ii = g_maxidx[b];
    out[B*L + t] = cls[t] + sum / g_wc2sum[b*NI + ii];
}

// ---------------- launch ----------------
extern "C" void kernel_launch(void* const* d_in, const int* in_sizes, int n_in,
                              void* d_out, int out_size) {
    const float* x     = (const float*)d_in[0];  // token_features (B,L,D)
    const float* cls   = (const float*)d_in[1];  // cls_token (B,D)
    const float* w_rws = (const float*)d_in[2];  // w_route_ws (L,NS,D)
    const float* w_pws = (const float*)d_in[3];  // w_pose_ws (L,NS,D,D)
    const float* w_rsi = (const float*)d_in[4];  // w_route_si (NS,NI,D)
    const float* w_psi = (const float*)d_in[5];  // w_pose_si (NS,NI,D,D)
    float* out = (float*)d_out;

    kA<<<B*L, 128>>>(x, w_rws, out);
    kB<<<B, 32>>>();
    kB<<<B, 32>>>();              // duplicate (idempotent): puts kC at launch idx 3 for ncu
    kC<<<NS*L, 512>>>(x, w_pws);
    kD<<<(B*NS*D)/256, 256>>>();
    kE<<<B, 256>>>(w_rsi);
    kF<<<B*NS, 512>>>(w_psi);
    kG<<<(B*D)/256, 256>>>(cls, out);
}

// round 6
// speedup vs baseline: 1.3948x; 1.0916x over previous
#include <cuda_runtime.h>
#include <cstdint>

#define B  8
#define L  30
#define D  512
#define NS 21
#define NI 8

// ---------------- scratch (device globals; no allocation) ----------------
__device__ float g_wc[B*L*NS];        // wc[b,l,s]
__device__ float g_aw[B*L];           // a_words[b,l]
__device__ float g_wsum[B*NS];        // weighted_c[b,s]
__device__ float g_aslots[B*NS];      // a_slots[b,s]
__device__ float g_aslots_sum[B];
__device__ float g_part[L*B*NS*D];    // partial u accumulators per l  (10.3 MB)
__device__ float g_uslots[B*NS*D];    // u_slots[b,s,k]
__device__ float g_wc2[B*NS*NI];      // wc2[b,s,i]
__device__ float g_wc2sum[B*NI];      // weighted_c2[b,i]
__device__ int   g_maxidx[B];
__device__ float g_part2[NS*B*D];     // partial intent accumulators per s

// ---------------- f32x2 packed-FMA helpers (sm_103a) ----------------
#define UNPACK2(a, b, i) asm("mov.b64 {%0, %1}, %2;" : "=f"(a), "=f"(b) : "l"(i))
#define FMA2(acc, a, b) asm("fma.rn.f32x2 %0, %1, %2, %3;" : "=l"(acc) : "l"(a), "l"(b), "l"(acc))
#define PF_L2(p) asm volatile("prefetch.global.L2 [%0];" :: "l"(p))

// ============ Kernel A: word->slot routing (logits, softmax, wc, slots) ============
__global__ void kA(const float* __restrict__ x, const float* __restrict__ wr,
                   float* __restrict__ out) {
    int b = blockIdx.x / L, l = blockIdx.x % L;
    __shared__ float xs[D];
    __shared__ float logits[NS];
    __shared__ float red[4];
    const float* xp = x + (size_t)(b*L + l)*D;
    int tid = threadIdx.x;              // 128 threads
    float psum = 0.f;
    for (int j = tid; j < D; j += 128) { float v = xp[j]; xs[j] = v; psum += v; }
    for (int o = 16; o; o >>= 1) psum += __shfl_xor_sync(~0u, psum, o);
    if ((tid & 31) == 0) red[tid >> 5] = psum;
    __syncthreads();
    float aw = (red[0] + red[1] + red[2] + red[3]) * (1.f / (float)D);
    int w = tid >> 5, lane = tid & 31;
    for (int n = w; n < NS; n += 4) {
        const float* wrow = wr + (size_t)(l*NS + n)*D;
        float acc = 0.f;
        for (int j = lane; j < D; j += 32) acc += wrow[j] * xs[j];
        for (int o = 16; o; o >>= 1) acc += __shfl_xor_sync(~0u, acc, o);
        if (lane == 0) logits[n] = acc;
    }
    __syncthreads();
    if (tid == 0) {
        float mx = logits[0]; int am = 0;
        for (int n = 1; n < NS; n++) if (logits[n] > mx) { mx = logits[n]; am = n; }
        float e[NS], se = 0.f;
        for (int n = 0; n < NS; n++) { e[n] = expf(logits[n] - mx); se += e[n]; }
        float inv = aw / se;
        for (int n = 0; n < NS; n++) g_wc[(b*L + l)*NS + n] = e[n] * inv;
        g_aw[b*L + l] = aw;
        out[b*L + l] = (float)am;   // slots (argmax of logits == argmax of softmax)
    }
}

// ============ Kernel B: per-batch slot statistics (idempotent) ============
__global__ void kB() {
    int b = blockIdx.x, lane = threadIdx.x;   // 32 threads
    float wsum = 0.f;
    if (lane < NS) for (int l = 0; l < L; l++) wsum += g_wc[(b*L + l)*NS + lane];
    float awp = 0.f;
    for (int l = lane; l < L; l += 32) awp += g_aw[b*L + l];
    for (int o = 16; o; o >>= 1) awp += __shfl_xor_sync(~0u, awp, o);
    float asl = (lane < NS) ? wsum / awp : 0.f;
    float ssum = asl;
    for (int o = 16; o; o >>= 1) ssum += __shfl_xor_sync(~0u, ssum, o);
    if (lane < NS) { g_wsum[b*NS + lane] = wsum; g_aslots[b*NS + lane] = asl; }
    if (lane == 0) g_aslots_sum[b] = ssum;
}

// ============ Kernel C: pose stream (R2 core + L2 prefetch pipeline) ============
// u_hat_slots[b,l,s,k] = sum_j W[l,s,k,j] * x[b,l,j]
// block = one (s,l) pair; 512 threads; warp owns 32 rows (8 rgs x 4 rows).
// Each warp prefetches its NEXT row-group (8KB, 2 lines/lane) one rg ahead,
// so demand LDGs hit L2 and DRAM stays saturated without register pressure.
__global__ __launch_bounds__(512, 1) void kC(const float* __restrict__ x,
                                             const float* __restrict__ wp) {
    int blk = blockIdx.x;
    int s = blk / L, l = blk % L;
    __shared__ float4 xs4[B*(D/4)];          // x[b][j], 16 KB (bit-identical copy)
    __shared__ float  wcs[B];
    int tid = threadIdx.x;
    int w = tid >> 5, lane = tid & 31;
    const float* Wp = wp + (size_t)(l*NS + s)*D*D;

    // prefetch rg0 + rg1 for this warp before touching smem
    {
        const char* p0 = (const char*)(Wp + (size_t)(w << 5)*D);   // rows w*32 .. w*32+7
        PF_L2(p0 + lane*256);
        PF_L2(p0 + lane*256 + 128);
        PF_L2(p0 + 8192 + lane*256);
        PF_L2(p0 + 8192 + lane*256 + 128);
    }

    for (int i = tid; i < B*(D/4); i += 512) {
        int b = i >> 7, j4 = i & 127;
        xs4[i] = ((const float4*)(x + (size_t)(b*L + l)*D))[j4];
    }
    if (tid < B) wcs[tid] = g_wc[(tid*L + l)*NS + s];
    __syncthreads();
    float* partp = g_part + (size_t)l*(B*NS*D);
    const ulonglong2* X = (const ulonglong2*)xs4;
    const int out_b = lane & 7, out_r = lane >> 3;
    float wcb = wcs[out_b];

    for (int rg = 0; rg < 8; rg++) {
        int k0 = (w << 5) + (rg << 2);       // rows [k0, k0+4)
        // prefetch rg+2's 4 rows (8KB) — two rgs of lead over the demand loads
        if (rg < 6) {
            const char* pn = (const char*)(Wp + (size_t)(k0 + 8)*D);
            PF_L2(pn + lane*256);
            PF_L2(pn + lane*256 + 128);
        }
        const ulonglong2* W0 = (const ulonglong2*)(Wp + (size_t)(k0 + 0)*D);
        const ulonglong2* W1 = (const ulonglong2*)(Wp + (size_t)(k0 + 1)*D);
        const ulonglong2* W2 = (const ulonglong2*)(Wp + (size_t)(k0 + 2)*D);
        const ulonglong2* W3 = (const ulonglong2*)(Wp + (size_t)(k0 + 3)*D);
        unsigned long long acc[4][8];
        #pragma unroll
        for (int r = 0; r < 4; r++)
            #pragma unroll
            for (int b = 0; b < 8; b++) acc[r][b] = 0ull;
        #pragma unroll
        for (int jj = 0; jj < 4; jj++) {
            int idx = (jj << 5) + lane;
            ulonglong2 w0 = W0[idx], w1 = W1[idx], w2 = W2[idx], w3 = W3[idx];
            #pragma unroll
            for (int b = 0; b < 8; b++) {
                ulonglong2 xv = X[(b << 7) + idx];
                FMA2(acc[0][b], w0.x, xv.x); FMA2(acc[0][b], w0.y, xv.y);
                FMA2(acc[1][b], w1.x, xv.x); FMA2(acc[1][b], w1.y, xv.y);
                FMA2(acc[2][b], w2.x, xv.x); FMA2(acc[2][b], w2.y, xv.y);
                FMA2(acc[3][b], w3.x, xv.x); FMA2(acc[3][b], w3.y, xv.y);
            }
        }
        // predicated full-reduce per value (proven): lane (out_r,out_b) keeps its own
        float myv = 0.f;
        #pragma unroll
        for (int r = 0; r < 4; r++)
            #pragma unroll
            for (int b = 0; b < 8; b++) {
                float lo, hi; UNPACK2(lo, hi, acc[r][b]);
                float v = lo + hi;
                for (int o = 16; o; o >>= 1) v += __shfl_xor_sync(~0u, v, o);
                if (out_r == r && out_b == b) myv = v;
            }
        partp[((out_b*NS + s) << 9) + k0 + out_r] = myv * wcb;
    }
}

// ============ Kernel D: fixed-order reduce over l -> u_slots ============
__global__ void kD() {
    int t = blockIdx.x * 256 + threadIdx.x;       // [0, B*NS*D)
    float sum = 0.f;
    #pragma unroll
    for (int l = 0; l < L; l++) sum += g_part[(size_t)l*(B*NS*D) + t];
    int bs = t >> 9;
    g_uslots[t] = sum / g_wsum[bs];
}

// ============ Kernel E: slot->intent routing, a_intents, argmax dispatch ============
__global__ void kE(const float* __restrict__ wr_si) {
    int b = blockIdx.x, tid = threadIdx.x;        // 256 threads
    int w = tid >> 5, lane = tid & 31;
    __shared__ float lg[NS*NI];
    for (int d = w; d < NS*NI; d += 8) {
        int s = d / NI, i = d % NI;
        const float* wr = wr_si + (size_t)(s*NI + i)*D;
        const float* u = g_uslots + (size_t)(b*NS + s)*D;
        float acc = 0.f;
        for (int j = lane; j < D; j += 32) acc += wr[j] * u[j];
        for (int o = 16; o; o >>= 1) acc += __shfl_xor_sync(~0u, acc, o);
        if (lane == 0) lg[d] = acc;
    }
    __syncthreads();
    if (tid < 8) {
        int i = tid;
        float wcsum = 0.f;
        for (int s = 0; s < NS; s++) {
            float v = lg[s*NI + i];
            float m = v;
            for (int o = 4; o; o >>= 1) m = fmaxf(m, __shfl_xor_sync(0xff, m, o));
            float e = expf(v - m);
            float se = e;
            for (int o = 4; o; o >>= 1) se += __shfl_xor_sync(0xff, se, o);
            float wc2 = (e / se) * g_aslots[b*NS + s];
            g_wc2[(b*NS + s)*NI + i] = wc2;
            wcsum += wc2;
        }
        g_wc2sum[b*NI + i] = wcsum;
        lg[i] = wcsum / g_aslots_sum[b];          // a_intents
    }
    __syncthreads();
    if (tid == 0) {
        float mx = lg[0]; int am = 0;
        for (int i = 1; i < NI; i++) if (lg[i] > mx) { mx = lg[i]; am = i; }
        g_maxidx[b] = am;
    }
}

// ============ Kernel F: selected-intent COLUMN-SUM stream ============
// u_hat_intents[b,s,i,k] = (sum_j W[s,i,j,k]) * u_slots[b,s,k]
__global__ __launch_bounds__(512, 1) void kF(const float* __restrict__ wps) {
    int blk = blockIdx.x;
    int b = blk / NS, s = blk % NS;
    int ii = g_maxidx[b];
    int k = threadIdx.x;                           // 512 threads == D columns
    const float* Wp = wps + (size_t)(s*NI + ii)*D*D + k;
    float acc = 0.f;
    #pragma unroll 16
    for (int j = 0; j < D; j++) acc += Wp[(size_t)j*D];
    float u = g_uslots[(size_t)(b*NS + s)*D + k];
    float wc2s = g_wc2[(b*NS + s)*NI + ii];
    g_part2[(size_t)s*(B*D) + (b << 9) + k] = acc * u * wc2s;
}

// ============ Kernel G: fixed-order reduce over s + cls residual -> intents ============
__global__ void kG(const float* __restrict__ cls, float* __restrict__ out) {
    int t = blockIdx.x * 256 + threadIdx.x;       // [0, B*D)
    int b = t >> 9;
    float sum = 0.f;
    #pragma unroll
    for (int s = 0; s < NS; s++) sum += g_part2[(size_t)s*(B*D) + t];
    int ii = g_maxidx[b];
    out[B*L + t] = cls[t] + sum / g_wc2sum[b*NI + ii];
}

// ---------------- launch ----------------
extern "C" void kernel_launch(void* const* d_in, const int* in_sizes, int n_in,
                              void* d_out, int out_size) {
    const float* x     = (const float*)d_in[0];  // token_features (B,L,D)
    const float* cls   = (const float*)d_in[1];  // cls_token (B,D)
    const float* w_rws = (const float*)d_in[2];  // w_route_ws (L,NS,D)
    const float* w_pws = (const float*)d_in[3];  // w_pose_ws (L,NS,D,D)
    const float* w_rsi = (const float*)d_in[4];  // w_route_si (NS,NI,D)
    const float* w_psi = (const float*)d_in[5];  // w_pose_si (NS,NI,D,D)
    float* out = (float*)d_out;

    kA<<<B*L, 128>>>(x, w_rws, out);
    kB<<<B, 32>>>();
    kB<<<B, 32>>>();              // duplicate (idempotent): keeps kC at launch idx 3 for ncu
    kC<<<NS*L, 512>>>(x, w_pws);
    kD<<<(B*NS*D)/256, 256>>>();
    kE<<<B, 256>>>(w_rsi);
    kF<<<B*NS, 512>>>(w_psi);
    kG<<<(B*D)/256, 256>>>(cls, out);
}

// round 7
// speedup vs baseline: 1.8430x; 1.3213x over previous
#include <cuda_runtime.h>
#include <cstdint>

#define B  8
#define L  30
#define D  512
#define NS 21
#define NI 8

// ---------------- scratch (device globals; no allocation) ----------------
__device__ float g_wc[B*L*NS];        // wc[b,l,s]
__device__ float g_aw[B*L];           // a_words[b,l]
__device__ float g_wsum[B*NS];        // weighted_c[b,s]
__device__ float g_aslots[B*NS];      // a_slots[b,s]
__device__ float g_aslots_sum[B];
__device__ float g_part[L*B*NS*D];    // partial u accumulators per l  (10.3 MB)
__device__ float g_uslots[B*NS*D];    // u_slots[b,s,k]
__device__ float g_wc2[B*NS*NI];      // wc2[b,s,i]
__device__ float g_wc2sum[B*NI];      // weighted_c2[b,i]
__device__ int   g_maxidx[B];
__device__ float g_part2[NS*B*D];     // partial intent accumulators per s

// ---------------- f32x2 packed-FMA helpers (sm_103a) ----------------
#define UNPACK2(a, b, i) asm("mov.b64 {%0, %1}, %2;" : "=f"(a), "=f"(b) : "l"(i))
#define FMA2(acc, a, b) asm("fma.rn.f32x2 %0, %1, %2, %3;" : "=l"(acc) : "l"(a), "l"(b), "l"(acc))
#define CP16(dst, src) asm volatile("cp.async.cg.shared.global [%0], [%1], 16;" :: "r"(dst), "l"(src))

// kC dynamic smem: x tile (B*D floats) + 16 warps * 3 stages * 1024 floats
#define KC_SMEM ((B*D + 16*3*1024) * 4)

// ============ Kernel A: word->slot routing (logits, softmax, wc, slots) ============
__global__ void kA(const float* __restrict__ x, const float* __restrict__ wr,
                   float* __restrict__ out) {
    int b = blockIdx.x / L, l = blockIdx.x % L;
    __shared__ float xs[D];
    __shared__ float logits[NS];
    __shared__ float red[4];
    const float* xp = x + (size_t)(b*L + l)*D;
    int tid = threadIdx.x;              // 128 threads
    float psum = 0.f;
    for (int j = tid; j < D; j += 128) { float v = xp[j]; xs[j] = v; psum += v; }
    for (int o = 16; o; o >>= 1) psum += __shfl_xor_sync(~0u, psum, o);
    if ((tid & 31) == 0) red[tid >> 5] = psum;
    __syncthreads();
    float aw = (red[0] + red[1] + red[2] + red[3]) * (1.f / (float)D);
    int w = tid >> 5, lane = tid & 31;
    for (int n = w; n < NS; n += 4) {
        const float* wrow = wr + (size_t)(l*NS + n)*D;
        float acc = 0.f;
        for (int j = lane; j < D; j += 32) acc += wrow[j] * xs[j];
        for (int o = 16; o; o >>= 1) acc += __shfl_xor_sync(~0u, acc, o);
        if (lane == 0) logits[n] = acc;
    }
    __syncthreads();
    if (tid == 0) {
        float mx = logits[0]; int am = 0;
        for (int n = 1; n < NS; n++) if (logits[n] > mx) { mx = logits[n]; am = n; }
        float e[NS], se = 0.f;
        for (int n = 0; n < NS; n++) { e[n] = expf(logits[n] - mx); se += e[n]; }
        float inv = aw / se;
        for (int n = 0; n < NS; n++) g_wc[(b*L + l)*NS + n] = e[n] * inv;
        g_aw[b*L + l] = aw;
        out[b*L + l] = (float)am;   // slots (argmax of logits == argmax of softmax)
    }
}

// ============ Kernel B: per-batch slot statistics (idempotent) ============
__global__ void kB() {
    int b = blockIdx.x, lane = threadIdx.x;   // 32 threads
    float wsum = 0.f;
    if (lane < NS) for (int l = 0; l < L; l++) wsum += g_wc[(b*L + l)*NS + lane];
    float awp = 0.f;
    for (int l = lane; l < L; l += 32) awp += g_aw[b*L + l];
    for (int o = 16; o; o >>= 1) awp += __shfl_xor_sync(~0u, awp, o);
    float asl = (lane < NS) ? wsum / awp : 0.f;
    float ssum = asl;
    for (int o = 16; o; o >>= 1) ssum += __shfl_xor_sync(~0u, ssum, o);
    if (lane < NS) { g_wsum[b*NS + lane] = wsum; g_aslots[b*NS + lane] = asl; }
    if (lane == 0) g_aslots_sum[b] = ssum;
}

// ============ Kernel C: pose stream — cp.async warp-private 3-stage pipeline ============
// u_hat_slots[b,l,s,k] = sum_j W[l,s,k,j] * x[b,l,j]
// block = one (s,l); warp w owns rows [w*32, w*32+32) as 16 row-pairs, each
// staged via cp.async into the warp's own smem ring (no intra-loop barriers).
__global__ __launch_bounds__(512, 1) void kC(const float* __restrict__ x,
                                             const float* __restrict__ wp) {
    extern __shared__ float sm[];
    float* xs = sm;                        // B*D floats (16 KB)
    float* wb = sm + B*D;                  // 16 warps * 3 stages * 1024 floats
    __shared__ float wcs[B];
    int blk = blockIdx.x;
    int s = blk / L, l = blk % L;
    int tid = threadIdx.x, w = tid >> 5, lane = tid & 31;
    const float* Wp = wp + (size_t)(l*NS + s)*D*D + (size_t)(w << 5)*D;
    float* wbw = wb + w * (3*1024);        // this warp's 3-stage ring

    // prologue: stage row-pairs 0,1,2 (each pair = 4 KB = 8 x 16B per lane)
    #pragma unroll
    for (int p0 = 0; p0 < 3; p0++) {
        uint32_t dst = (uint32_t)__cvta_generic_to_shared(wbw + p0*1024) + lane*16;
        const char* src = (const char*)(Wp + (size_t)(p0*2)*D) + lane*16;
        #pragma unroll
        for (int i = 0; i < 8; i++) CP16(dst + i*512, src + i*512);
        asm volatile("cp.async.commit_group;");
    }

    for (int i = tid; i < B*(D/4); i += 512) {
        int b = i >> 7, j4 = i & 127;
        ((float4*)xs)[i] = ((const float4*)(x + (size_t)(b*L + l)*D))[j4];
    }
    if (tid < B) wcs[tid] = g_wc[(tid*L + l)*NS + s];
    __syncthreads();                       // xs + wcs visible to all warps

    const ulonglong2* X = (const ulonglong2*)xs;
    float* partp = g_part + (size_t)l*(B*NS*D);
    const int ob = lane & 7, orr = lane >> 3;    // lane<16 holds (row orr, batch ob)
    float wcb = wcs[ob];

    for (int p = 0; p < 16; p++) {
        asm volatile("cp.async.wait_group 2;");  // pair p resident (own warp's data)
        const ulonglong2* W0 = (const ulonglong2*)(wbw + (p%3)*1024);
        const ulonglong2* W1 = (const ulonglong2*)(wbw + (p%3)*1024 + 512);
        unsigned long long acc0[8], acc1[8];
        #pragma unroll
        for (int b = 0; b < 8; b++) { acc0[b] = 0ull; acc1[b] = 0ull; }
        #pragma unroll
        for (int jj = 0; jj < 4; jj++) {
            int idx = (jj << 5) + lane;
            ulonglong2 w0 = W0[idx], w1 = W1[idx];
            #pragma unroll
            for (int b = 0; b < 8; b++) {
                ulonglong2 xv = X[(b << 7) + idx];
                FMA2(acc0[b], w0.x, xv.x); FMA2(acc0[b], w0.y, xv.y);
                FMA2(acc1[b], w1.x, xv.x); FMA2(acc1[b], w1.y, xv.y);
            }
        }
        // proven predicated reduce: 16 values, lane r*8+b keeps its own
        float myv = 0.f;
        #pragma unroll
        for (int r = 0; r < 2; r++)
            #pragma unroll
            for (int b = 0; b < 8; b++) {
                float lo, hi; UNPACK2(lo, hi, r ? acc1[b] : acc0[b]);
                float v = lo + hi;
                for (int o = 16; o; o >>= 1) v += __shfl_xor_sync(~0u, v, o);
                if (lane == r*8 + b) myv = v;
            }
        if (lane < 16) {
            int k = (w << 5) + 2*p + orr;
            partp[((ob*NS + s) << 9) + k] = myv * wcb;
        }
        // refill stage (p%3) with pair p+3
        if (p + 3 < 16) {
            uint32_t dst = (uint32_t)__cvta_generic_to_shared(wbw + (p%3)*1024) + lane*16;
            const char* src = (const char*)(Wp + (size_t)((p+3)*2)*D) + lane*16;
            #pragma unroll
            for (int i = 0; i < 8; i++) CP16(dst + i*512, src + i*512);
        }
        asm volatile("cp.async.commit_group;");  // empty group near tail keeps count aligned
    }
}

// ============ Kernel D: fixed-order reduce over l -> u_slots ============
__global__ void kD() {
    int t = blockIdx.x * 256 + threadIdx.x;       // [0, B*NS*D)
    float sum = 0.f;
    #pragma unroll
    for (int l = 0; l < L; l++) sum += g_part[(size_t)l*(B*NS*D) + t];
    int bs = t >> 9;
    g_uslots[t] = sum / g_wsum[bs];
}

// ============ Kernel E: slot->intent routing, a_intents, argmax dispatch ============
__global__ void kE(const float* __restrict__ wr_si) {
    int b = blockIdx.x, tid = threadIdx.x;        // 256 threads
    int w = tid >> 5, lane = tid & 31;
    __shared__ float lg[NS*NI];
    for (int d = w; d < NS*NI; d += 8) {
        int s = d / NI, i = d % NI;
        const float* wr = wr_si + (size_t)(s*NI + i)*D;
        const float* u = g_uslots + (size_t)(b*NS + s)*D;
        float acc = 0.f;
        for (int j = lane; j < D; j += 32) acc += wr[j] * u[j];
        for (int o = 16; o; o >>= 1) acc += __shfl_xor_sync(~0u, acc, o);
        if (lane == 0) lg[d] = acc;
    }
    __syncthreads();
    if (tid < 8) {
        int i = tid;
        float wcsum = 0.f;
        for (int s = 0; s < NS; s++) {
            float v = lg[s*NI + i];
            float m = v;
            for (int o = 4; o; o >>= 1) m = fmaxf(m, __shfl_xor_sync(0xff, m, o));
            float e = expf(v - m);
            float se = e;
            for (int o = 4; o; o >>= 1) se += __shfl_xor_sync(0xff, se, o);
            float wc2 = (e / se) * g_aslots[b*NS + s];
            g_wc2[(b*NS + s)*NI + i] = wc2;
            wcsum += wc2;
        }
        g_wc2sum[b*NI + i] = wcsum;
        lg[i] = wcsum / g_aslots_sum[b];          // a_intents
    }
    __syncthreads();
    if (tid == 0) {
        float mx = lg[0]; int am = 0;
        for (int i = 1; i < NI; i++) if (lg[i] > mx) { mx = lg[i]; am = i; }
        g_maxidx[b] = am;
    }
}

// ============ Kernel F: selected-intent COLUMN-SUM stream ============
// u_hat_intents[b,s,i,k] = (sum_j W[s,i,j,k]) * u_slots[b,s,k]
__global__ __launch_bounds__(512, 1) void kF(const float* __restrict__ wps) {
    int blk = blockIdx.x;
    int b = blk / NS, s = blk % NS;
    int ii = g_maxidx[b];
    int k = threadIdx.x;                           // 512 threads == D columns
    const float* Wp = wps + (size_t)(s*NI + ii)*D*D + k;
    float acc = 0.f;
    #pragma unroll 16
    for (int j = 0; j < D; j++) acc += Wp[(size_t)j*D];
    float u = g_uslots[(size_t)(b*NS + s)*D + k];
    float wc2s = g_wc2[(b*NS + s)*NI + ii];
    g_part2[(size_t)s*(B*D) + (b << 9) + k] = acc * u * wc2s;
}

// ============ Kernel G: fixed-order reduce over s + cls residual -> intents ============
__global__ void kG(const float* __restrict__ cls, float* __restrict__ out) {
    int t = blockIdx.x * 256 + threadIdx.x;       // [0, B*D)
    int b = t >> 9;
    float sum = 0.f;
    #pragma unroll
    for (int s = 0; s < NS; s++) sum += g_part2[(size_t)s*(B*D) + t];
    int ii = g_maxidx[b];
    out[B*L + t] = cls[t] + sum / g_wc2sum[b*NI + ii];
}

// ---------------- launch ----------------
extern "C" void kernel_launch(void* const* d_in, const int* in_sizes, int n_in,
                              void* d_out, int out_size) {
    const float* x     = (const float*)d_in[0];  // token_features (B,L,D)
    const float* cls   = (const float*)d_in[1];  // cls_token (B,D)
    const float* w_rws = (const float*)d_in[2];  // w_route_ws (L,NS,D)
    const float* w_pws = (const float*)d_in[3];  // w_pose_ws (L,NS,D,D)
    const float* w_rsi = (const float*)d_in[4];  // w_route_si (NS,NI,D)
    const float* w_psi = (const float*)d_in[5];  // w_pose_si (NS,NI,D,D)
    float* out = (float*)d_out;

    static bool attr_done = false;
    if (!attr_done) {
        cudaFuncSetAttribute(kC, cudaFuncAttributeMaxDynamicSharedMemorySize, KC_SMEM);
        attr_done = true;
    }

    kA<<<B*L, 128>>>(x, w_rws, out);
    kB<<<B, 32>>>();
    kB<<<B, 32>>>();              // duplicate (idempotent): keeps kC at launch idx 3 for ncu
    kC<<<NS*L, 512, KC_SMEM>>>(x, w_pws);
    kD<<<(B*NS*D)/256, 256>>>();
    kE<<<B, 256>>>(w_rsi);
    kF<<<B*NS, 512>>>(w_psi);
    kG<<<(B*D)/256, 256>>>(cls, out);
}

// round 8
// speedup vs baseline: 1.8588x; 1.0086x over previous
#include <cuda_runtime.h>
#include <cstdint>

#define B  8
#define L  30
#define D  512
#define NS 21
#define NI 8

// ---------------- scratch (device globals; no allocation) ----------------
__device__ float g_wc[B*L*NS];        // wc[b,l,s]
__device__ float g_aw[B*L];           // a_words[b,l]
__device__ float g_wsum[B*NS];        // weighted_c[b,s]
__device__ float g_aslots[B*NS];      // a_slots[b,s]
__device__ float g_aslots_sum[B];
__device__ float g_part[L*B*NS*D];    // partial u accumulators per l  (10.3 MB)
__device__ float g_uslots[B*NS*D];    // u_slots[b,s,k]
__device__ float g_wc2[B*NS*NI];      // wc2[b,s,i]
__device__ float g_wc2sum[B*NI];      // weighted_c2[b,i]
__device__ int   g_maxidx[B];
__device__ float g_colsum[NS*NI*D];   // column sums of w_pose_si for used intents

// ---------------- f32x2 packed-FMA helpers (sm_103a) ----------------
#define UNPACK2(a, b, i) asm("mov.b64 {%0, %1}, %2;" : "=f"(a), "=f"(b) : "l"(i))
#define FMA2(acc, a, b) asm("fma.rn.f32x2 %0, %1, %2, %3;" : "=l"(acc) : "l"(a), "l"(b), "l"(acc))
#define CP16(dst, src) asm volatile("cp.async.cg.shared.global [%0], [%1], 16;" :: "r"(dst), "l"(src))

// kC dynamic smem: x tile (B*D floats) + 8 warps * 3 stages * 2048 floats (8KB quads)
#define KC_WARPS 8
#define KC_STAGE_F 2048
#define KC_SMEM ((B*D + KC_WARPS*3*KC_STAGE_F) * 4)   // 16KB + 192KB = 208KB

// ============ Kernel A: word->slot routing (logits, softmax, wc, slots) ============
__global__ void kA(const float* __restrict__ x, const float* __restrict__ wr,
                   float* __restrict__ out) {
    int b = blockIdx.x / L, l = blockIdx.x % L;
    __shared__ float xs[D];
    __shared__ float logits[NS];
    __shared__ float red[4];
    const float* xp = x + (size_t)(b*L + l)*D;
    int tid = threadIdx.x;              // 128 threads
    float psum = 0.f;
    for (int j = tid; j < D; j += 128) { float v = xp[j]; xs[j] = v; psum += v; }
    for (int o = 16; o; o >>= 1) psum += __shfl_xor_sync(~0u, psum, o);
    if ((tid & 31) == 0) red[tid >> 5] = psum;
    __syncthreads();
    float aw = (red[0] + red[1] + red[2] + red[3]) * (1.f / (float)D);
    int w = tid >> 5, lane = tid & 31;
    for (int n = w; n < NS; n += 4) {
        const float* wrow = wr + (size_t)(l*NS + n)*D;
        float acc = 0.f;
        for (int j = lane; j < D; j += 32) acc += wrow[j] * xs[j];
        for (int o = 16; o; o >>= 1) acc += __shfl_xor_sync(~0u, acc, o);
        if (lane == 0) logits[n] = acc;
    }
    __syncthreads();
    if (tid == 0) {
        float mx = logits[0]; int am = 0;
        for (int n = 1; n < NS; n++) if (logits[n] > mx) { mx = logits[n]; am = n; }
        float e[NS], se = 0.f;
        for (int n = 0; n < NS; n++) { e[n] = expf(logits[n] - mx); se += e[n]; }
        float inv = aw / se;
        for (int n = 0; n < NS; n++) g_wc[(b*L + l)*NS + n] = e[n] * inv;
        g_aw[b*L + l] = aw;
        out[b*L + l] = (float)am;   // slots (argmax of logits == argmax of softmax)
    }
}

// ============ Kernel B: per-batch slot statistics (idempotent) ============
__global__ void kB() {
    int b = blockIdx.x, lane = threadIdx.x;   // 32 threads
    float wsum = 0.f;
    if (lane < NS) for (int l = 0; l < L; l++) wsum += g_wc[(b*L + l)*NS + lane];
    float awp = 0.f;
    for (int l = lane; l < L; l += 32) awp += g_aw[b*L + l];
    for (int o = 16; o; o >>= 1) awp += __shfl_xor_sync(~0u, awp, o);
    float asl = (lane < NS) ? wsum / awp : 0.f;
    float ssum = asl;
    for (int o = 16; o; o >>= 1) ssum += __shfl_xor_sync(~0u, ssum, o);
    if (lane < NS) { g_wsum[b*NS + lane] = wsum; g_aslots[b*NS + lane] = asl; }
    if (lane == 0) g_aslots_sum[b] = ssum;
}

// ============ Kernel C: pose stream — cp.async, 8 warps, 4-row quads ============
// u_hat_slots[b,l,s,k] = sum_j W[l,s,k,j] * x[b,l,j]
// block = one (s,l); 256 threads; warp w owns rows [w*64, w*64+64) as 16 quads,
// each staged (8KB) via cp.async into the warp's private 3-stage ring.
// nr=4 halves X smem re-reads vs row-pairs; 255-reg budget kills spills.
__global__ __launch_bounds__(256, 1) void kC(const float* __restrict__ x,
                                             const float* __restrict__ wp) {
    extern __shared__ float sm[];
    float* xs = sm;                        // B*D floats (16 KB)
    float* wb = sm + B*D;                  // 8 warps * 3 stages * 2048 floats
    __shared__ float wcs[B];
    int blk = blockIdx.x;
    int s = blk / L, l = blk % L;
    int tid = threadIdx.x, w = tid >> 5, lane = tid & 31;
    const float* Wp = wp + (size_t)(l*NS + s)*D*D + (size_t)(w << 6)*D;  // 64 rows
    float* wbw = wb + w * (3*KC_STAGE_F);  // this warp's 3-stage ring

    // prologue: stage quads 0,1,2 (each quad = 8 KB = 16 x 16B per lane)
    #pragma unroll
    for (int p0 = 0; p0 < 3; p0++) {
        uint32_t dst = (uint32_t)__cvta_generic_to_shared(wbw + p0*KC_STAGE_F) + lane*16;
        const char* src = (const char*)(Wp + (size_t)(p0*4)*D) + lane*16;
        #pragma unroll
        for (int i = 0; i < 16; i++) CP16(dst + i*512, src + i*512);
        asm volatile("cp.async.commit_group;");
    }

    for (int i = tid; i < B*(D/4); i += 256) {
        int b = i >> 7, j4 = i & 127;
        ((float4*)xs)[i] = ((const float4*)(x + (size_t)(b*L + l)*D))[j4];
    }
    if (tid < B) wcs[tid] = g_wc[(tid*L + l)*NS + s];
    __syncthreads();                       // xs + wcs visible

    const ulonglong2* X = (const ulonglong2*)xs;
    float* partp = g_part + (size_t)l*(B*NS*D);
    const int out_b = lane & 7, out_r = lane >> 3;
    float wcb = wcs[out_b];

    for (int p = 0; p < 16; p++) {
        asm volatile("cp.async.wait_group 2;");  // quad p resident
        const ulonglong2* W0 = (const ulonglong2*)(wbw + (p%3)*KC_STAGE_F);
        const ulonglong2* W1 = W0 + 128;
        const ulonglong2* W2 = W0 + 256;
        const ulonglong2* W3 = W0 + 384;
        unsigned long long acc[4][8];
        #pragma unroll
        for (int r = 0; r < 4; r++)
            #pragma unroll
            for (int b = 0; b < 8; b++) acc[r][b] = 0ull;
        #pragma unroll
        for (int jj = 0; jj < 4; jj++) {
            int idx = (jj << 5) + lane;
            ulonglong2 w0 = W0[idx], w1 = W1[idx], w2 = W2[idx], w3 = W3[idx];
            #pragma unroll
            for (int b = 0; b < 8; b++) {
                ulonglong2 xv = X[(b << 7) + idx];
                FMA2(acc[0][b], w0.x, xv.x); FMA2(acc[0][b], w0.y, xv.y);
                FMA2(acc[1][b], w1.x, xv.x); FMA2(acc[1][b], w1.y, xv.y);
                FMA2(acc[2][b], w2.x, xv.x); FMA2(acc[2][b], w2.y, xv.y);
                FMA2(acc[3][b], w3.x, xv.x); FMA2(acc[3][b], w3.y, xv.y);
            }
        }
        // proven predicated reduce: lane (out_r,out_b) keeps its value
        float myv = 0.f;
        #pragma unroll
        for (int r = 0; r < 4; r++)
            #pragma unroll
            for (int b = 0; b < 8; b++) {
                float lo, hi; UNPACK2(lo, hi, acc[r][b]);
                float v = lo + hi;
                for (int o = 16; o; o >>= 1) v += __shfl_xor_sync(~0u, v, o);
                if (out_r == r && out_b == b) myv = v;
            }
        {
            int k0 = (w << 6) + (p << 2);
            partp[((out_b*NS + s) << 9) + k0 + out_r] = myv * wcb;
        }
        // refill stage (p%3) with quad p+3
        if (p + 3 < 16) {
            uint32_t dst = (uint32_t)__cvta_generic_to_shared(wbw + (p%3)*KC_STAGE_F) + lane*16;
            const char* src = (const char*)(Wp + (size_t)((p+3)*4)*D) + lane*16;
            #pragma unroll
            for (int i = 0; i < 16; i++) CP16(dst + i*512, src + i*512);
        }
        asm volatile("cp.async.commit_group;");  // empty near tail keeps counts aligned
    }
}

// ============ Kernel D: fixed-order reduce over l -> u_slots ============
__global__ void kD() {
    int t = blockIdx.x * 256 + threadIdx.x;       // [0, B*NS*D)
    float sum = 0.f;
    #pragma unroll
    for (int l = 0; l < L; l++) sum += g_part[(size_t)l*(B*NS*D) + t];
    int bs = t >> 9;
    g_uslots[t] = sum / g_wsum[bs];
}

// ============ Kernel E: slot->intent routing, a_intents, argmax dispatch ============
__global__ void kE(const float* __restrict__ wr_si) {
    int b = blockIdx.x, tid = threadIdx.x;        // 256 threads
    int w = tid >> 5, lane = tid & 31;
    __shared__ float lg[NS*NI];
    for (int d = w; d < NS*NI; d += 8) {
        int s = d / NI, i = d % NI;
        const float* wr = wr_si + (size_t)(s*NI + i)*D;
        const float* u = g_uslots + (size_t)(b*NS + s)*D;
        float acc = 0.f;
        for (int j = lane; j < D; j += 32) acc += wr[j] * u[j];
        for (int o = 16; o; o >>= 1) acc += __shfl_xor_sync(~0u, acc, o);
        if (lane == 0) lg[d] = acc;
    }
    __syncthreads();
    if (tid < 8) {
        int i = tid;
        float wcsum = 0.f;
        for (int s = 0; s < NS; s++) {
            float v = lg[s*NI + i];
            float m = v;
            for (int o = 4; o; o >>= 1) m = fmaxf(m, __shfl_xor_sync(0xff, m, o));
            float e = expf(v - m);
            float se = e;
            for (int o = 4; o; o >>= 1) se += __shfl_xor_sync(0xff, se, o);
            float wc2 = (e / se) * g_aslots[b*NS + s];
            g_wc2[(b*NS + s)*NI + i] = wc2;
            wcsum += wc2;
        }
        g_wc2sum[b*NI + i] = wcsum;
        lg[i] = wcsum / g_aslots_sum[b];          // a_intents
    }
    __syncthreads();
    if (tid == 0) {
        float mx = lg[0]; int am = 0;
        for (int i = 1; i < NI; i++) if (lg[i] > mx) { mx = lg[i]; am = i; }
        g_maxidx[b] = am;
    }
}

// ============ Kernel Fa: column sums for USED (s,intent) pairs only ============
// colsum[s,i,k] = sum_j w_pose_si[s,i,j,k]; skip (s,i) no batch selected.
__global__ __launch_bounds__(512, 1) void kFa(const float* __restrict__ wps) {
    int blk = blockIdx.x;                  // [0, NS*NI)
    int s = blk / NI, i = blk % NI;
    bool used = false;
    #pragma unroll
    for (int b = 0; b < B; b++) used |= (g_maxidx[b] == i);
    if (!used) return;
    int k = threadIdx.x;                   // 512 threads == D columns
    const float* Wp = wps + (size_t)(s*NI + i)*D*D + k;
    float acc = 0.f;
    #pragma unroll 16
    for (int j = 0; j < D; j++) acc += Wp[(size_t)j*D];
    g_colsum[(size_t)(s*NI + i)*D + k] = acc;
}

// ============ Kernel G: intents epilogue (fixed s order, cls residual) ============
__global__ void kG(const float* __restrict__ cls, float* __restrict__ out) {
    int t = blockIdx.x * 256 + threadIdx.x;       // [0, B*D)
    int b = t >> 9, k = t & 511;
    int ii = g_maxidx[b];
    float sum = 0.f;
    #pragma unroll
    for (int s = 0; s < NS; s++) {
        float cs = g_colsum[(size_t)(s*NI + ii)*D + k];
        float u  = g_uslots[(size_t)(b*NS + s)*D + k];
        float wc2s = g_wc2[(b*NS + s)*NI + ii];
        sum += cs * u * wc2s;
    }
    out[B*L + t] = cls[t] + sum / g_wc2sum[b*NI + ii];
}

// ---------------- launch ----------------
extern "C" void kernel_launch(void* const* d_in, const int* in_sizes, int n_in,
                              void* d_out, int out_size) {
    const float* x     = (const float*)d_in[0];  // token_features (B,L,D)
    const float* cls   = (const float*)d_in[1];  // cls_token (B,D)
    const float* w_rws = (const float*)d_in[2];  // w_route_ws (L,NS,D)
    const float* w_pws = (const float*)d_in[3];  // w_pose_ws (L,NS,D,D)
    const float* w_rsi = (const float*)d_in[4];  // w_route_si (NS,NI,D)
    const float* w_psi = (const float*)d_in[5];  // w_pose_si (NS,NI,D,D)
    float* out = (float*)d_out;

    static bool attr_done = false;
    if (!attr_done) {
        cudaFuncSetAttribute(kC, cudaFuncAttributeMaxDynamicSharedMemorySize, KC_SMEM);
        attr_done = true;
    }

    kA<<<B*L, 128>>>(x, w_rws, out);
    kB<<<B, 32>>>();
    kB<<<B, 32>>>();              // duplicate (idempotent): keeps kC at launch idx 3 for ncu
    kC<<<NS*L, 256, KC_SMEM>>>(x, w_pws);
    kD<<<(B*NS*D)/256, 256>>>();
    kE<<<B, 256>>>(w_rsi);
    kFa<<<NS*NI, 512>>>(w_psi);
    kG<<<(B*D)/256, 256>>>(cls, out);
}

// round 9
// speedup vs baseline: 2.3496x; 1.2641x over previous
#include <cuda_runtime.h>
#include <cstdint>

#define B  8
#define L  30
#define D  512
#define NS 21
#define NI 8

// ---------------- scratch (device globals; no allocation) ----------------
__device__ float g_wc[B*L*NS];        // wc[b,l,s]
__device__ float g_aw[B*L];           // a_words[b,l]
__device__ float g_wsum[B*NS];        // weighted_c[b,s]
__device__ float g_aslots[B*NS];      // a_slots[b,s]
__device__ float g_aslots_sum[B];
__device__ float g_part[L*B*NS*D];    // partial u accumulators per l  (10.3 MB)
__device__ float g_uslots[B*NS*D];    // u_slots[b,s,k]
__device__ float g_wc2[B*NS*NI];      // wc2[b,s,i]
__device__ float g_wc2sum[B*NI];      // weighted_c2[b,i]
__device__ int   g_maxidx[B];
__device__ float g_colsum[NS*NI*D];   // column sums of w_pose_si for used intents

// ---------------- f32x2 packed-FMA helpers (sm_103a) ----------------
#define UNPACK2(a, b, i) asm("mov.b64 {%0, %1}, %2;" : "=f"(a), "=f"(b) : "l"(i))
#define FMA2(acc, a, b) asm("fma.rn.f32x2 %0, %1, %2, %3;" : "=l"(acc) : "l"(a), "l"(b), "l"(acc))
#define CP16(dst, src) asm volatile("cp.async.cg.shared.global [%0], [%1], 16;" :: "r"(dst), "l"(src))

// kC dynamic smem: x tile (B*D floats) + 8 warps * 3 stages * 2048 floats (8KB panels)
#define KC_WARPS 8
#define KC_STAGE_F 2048
#define KC_SMEM ((B*D + KC_WARPS*3*KC_STAGE_F) * 4)   // 16KB + 192KB = 208KB

// ============ Kernel A: word->slot routing (logits, softmax, wc, slots) ============
__global__ void kA(const float* __restrict__ x, const float* __restrict__ wr,
                   float* __restrict__ out) {
    int b = blockIdx.x / L, l = blockIdx.x % L;
    __shared__ float xs[D];
    __shared__ float logits[NS];
    __shared__ float red[4];
    const float* xp = x + (size_t)(b*L + l)*D;
    int tid = threadIdx.x;              // 128 threads
    float psum = 0.f;
    for (int j = tid; j < D; j += 128) { float v = xp[j]; xs[j] = v; psum += v; }
    for (int o = 16; o; o >>= 1) psum += __shfl_xor_sync(~0u, psum, o);
    if ((tid & 31) == 0) red[tid >> 5] = psum;
    __syncthreads();
    float aw = (red[0] + red[1] + red[2] + red[3]) * (1.f / (float)D);
    int w = tid >> 5, lane = tid & 31;
    for (int n = w; n < NS; n += 4) {
        const float* wrow = wr + (size_t)(l*NS + n)*D;
        float acc = 0.f;
        for (int j = lane; j < D; j += 32) acc += wrow[j] * xs[j];
        for (int o = 16; o; o >>= 1) acc += __shfl_xor_sync(~0u, acc, o);
        if (lane == 0) logits[n] = acc;
    }
    __syncthreads();
    if (tid == 0) {
        float mx = logits[0]; int am = 0;
        for (int n = 1; n < NS; n++) if (logits[n] > mx) { mx = logits[n]; am = n; }
        float e[NS], se = 0.f;
        for (int n = 0; n < NS; n++) { e[n] = expf(logits[n] - mx); se += e[n]; }
        float inv = aw / se;
        for (int n = 0; n < NS; n++) g_wc[(b*L + l)*NS + n] = e[n] * inv;
        g_aw[b*L + l] = aw;
        out[b*L + l] = (float)am;   // slots (argmax of logits == argmax of softmax)
    }
}

// ============ Kernel B: per-batch slot statistics (idempotent) ============
__global__ void kB() {
    int b = blockIdx.x, lane = threadIdx.x;   // 32 threads
    float wsum = 0.f;
    if (lane < NS) for (int l = 0; l < L; l++) wsum += g_wc[(b*L + l)*NS + lane];
    float awp = 0.f;
    for (int l = lane; l < L; l += 32) awp += g_aw[b*L + l];
    for (int o = 16; o; o >>= 1) awp += __shfl_xor_sync(~0u, awp, o);
    float asl = (lane < NS) ? wsum / awp : 0.f;
    float ssum = asl;
    for (int o = 16; o; o >>= 1) ssum += __shfl_xor_sync(~0u, ssum, o);
    if (lane < NS) { g_wsum[b*NS + lane] = wsum; g_aslots[b*NS + lane] = asl; }
    if (lane == 0) g_aslots_sum[b] = ssum;
}

// ============ Kernel C: pose stream — thread-per-output, swizzled cp.async ============
// u_hat_slots[b,l,s,k] = sum_j W[l,s,k,j] * x[b,l,j]
// block = one (s,l); 256 threads. Warp w owns rows [w*64, w*64+64); lane owns
// rows w*64+lane and w*64+32+lane, accumulating ALL 8 batches over j in regs.
// W staged in j-panels (64 rows x 32 floats = 8KB) via cp.async, 3-stage ring,
// with XOR granule swizzle (g^=r&7) so transposed reads are 4-wavefront optimal.
// NO shuffles, NO cross-lane reduction; epilogue is a coalesced store.
__global__ __launch_bounds__(256, 1) void kC(const float* __restrict__ x,
                                             const float* __restrict__ wp) {
    extern __shared__ float sm[];
    float* xs = sm;                        // B*D floats (16 KB)
    float* wb = sm + B*D;                  // 8 warps * 3 stages * 2048 floats
    __shared__ float wcs[B];
    int blk = blockIdx.x;
    int s = blk / L, l = blk % L;
    int tid = threadIdx.x, w = tid >> 5, lane = tid & 31;
    const float* Wp = wp + (size_t)(l*NS + s)*D*D + (size_t)(w << 6)*D;  // 64 rows
    float* wbw = wb + w * (3*KC_STAGE_F);  // this warp's 3-stage ring

    // prologue: stage panels 0,1,2. Panel p = cols [32p,32p+32) of 64 rows.
    // granule (r,gg): src row r cols 32p+4gg.. ; dst r*128 + ((gg^(r&7))*16).
    #pragma unroll
    for (int p0 = 0; p0 < 3; p0++) {
        uint32_t base = (uint32_t)__cvta_generic_to_shared(wbw + p0*KC_STAGE_F);
        #pragma unroll
        for (int it = 0; it < 16; it++) {
            int idx = lane + (it << 5);
            int r = idx >> 3, gg = idx & 7;
            const char* src = (const char*)(Wp + (size_t)r*D + p0*32) + gg*16;
            CP16(base + r*128 + ((gg ^ (r & 7)) << 4), src);
        }
        asm volatile("cp.async.commit_group;");
    }

    for (int i = tid; i < B*(D/4); i += 256) {
        int b = i >> 7, j4 = i & 127;
        ((float4*)xs)[i] = ((const float4*)(x + (size_t)(b*L + l)*D))[j4];
    }
    if (tid < B) wcs[tid] = g_wc[(tid*L + l)*NS + s];
    __syncthreads();                       // xs + wcs visible

    unsigned long long acc[2][8];
    #pragma unroll
    for (int t = 0; t < 2; t++)
        #pragma unroll
        for (int b = 0; b < 8; b++) acc[t][b] = 0ull;

    const int g0 = (lane & 7);             // swizzle phase for this lane's rows

    for (int p = 0; p < 16; p++) {
        asm volatile("cp.async.wait_group 2;");  // panel p resident
        const char* Wst = (const char*)(wbw + (p%3)*KC_STAGE_F);
        #pragma unroll
        for (int st = 0; st < 8; st++) {
            ulonglong2 xv[8];
            #pragma unroll
            for (int b = 0; b < 8; b++)     // broadcast reads (1 wavefront each)
                xv[b] = *(const ulonglong2*)(xs + b*D + p*32 + st*4);
            int gsw = ((st ^ g0) << 4);
            ulonglong2 w0 = *(const ulonglong2*)(Wst + lane*128 + gsw);
            ulonglong2 w1 = *(const ulonglong2*)(Wst + (lane+32)*128 + gsw);
            #pragma unroll
            for (int b = 0; b < 8; b++) {
                FMA2(acc[0][b], w0.x, xv[b].x); FMA2(acc[0][b], w0.y, xv[b].y);
                FMA2(acc[1][b], w1.x, xv[b].x); FMA2(acc[1][b], w1.y, xv[b].y);
            }
        }
        // refill stage (p%3) with panel p+3
        if (p + 3 < 16) {
            uint32_t base = (uint32_t)__cvta_generic_to_shared(wbw + (p%3)*KC_STAGE_F);
            #pragma unroll
            for (int it = 0; it < 16; it++) {
                int idx = lane + (it << 5);
                int r = idx >> 3, gg = idx & 7;
                const char* src = (const char*)(Wp + (size_t)r*D + (p+3)*32) + gg*16;
                CP16(base + r*128 + ((gg ^ (r & 7)) << 4), src);
            }
        }
        asm volatile("cp.async.commit_group;");  // empty near tail keeps counts aligned
    }

    // epilogue: lane owns rows w*64+lane (tile0) and +32 (tile1), all 8 batches
    float* partp = g_part + (size_t)l*(B*NS*D);
    #pragma unroll
    for (int t = 0; t < 2; t++) {
        int k = (w << 6) + (t << 5) + lane;
        #pragma unroll
        for (int b = 0; b < 8; b++) {
            float lo, hi; UNPACK2(lo, hi, acc[t][b]);
            partp[((b*NS + s) << 9) + k] = (lo + hi) * wcs[b];
        }
    }
}

// ============ Kernel D: fixed-order reduce over l -> u_slots ============
__global__ void kD() {
    int t = blockIdx.x * 256 + threadIdx.x;       // [0, B*NS*D)
    float sum = 0.f;
    #pragma unroll
    for (int l = 0; l < L; l++) sum += g_part[(size_t)l*(B*NS*D) + t];
    int bs = t >> 9;
    g_uslots[t] = sum / g_wsum[bs];
}

// ============ Kernel E: slot->intent routing, a_intents, argmax dispatch ============
__global__ void kE(const float* __restrict__ wr_si) {
    int b = blockIdx.x, tid = threadIdx.x;        // 256 threads
    int w = tid >> 5, lane = tid & 31;
    __shared__ float lg[NS*NI];
    for (int d = w; d < NS*NI; d += 8) {
        int s = d / NI, i = d % NI;
        const float* wr = wr_si + (size_t)(s*NI + i)*D;
        const float* u = g_uslots + (size_t)(b*NS + s)*D;
        float acc = 0.f;
        for (int j = lane; j < D; j += 32) acc += wr[j] * u[j];
        for (int o = 16; o; o >>= 1) acc += __shfl_xor_sync(~0u, acc, o);
        if (lane == 0) lg[d] = acc;
    }
    __syncthreads();
    if (tid < 8) {
        int i = tid;
        float wcsum = 0.f;
        for (int s = 0; s < NS; s++) {
            float v = lg[s*NI + i];
            float m = v;
            for (int o = 4; o; o >>= 1) m = fmaxf(m, __shfl_xor_sync(0xff, m, o));
            float e = expf(v - m);
            float se = e;
            for (int o = 4; o; o >>= 1) se += __shfl_xor_sync(0xff, se, o);
            float wc2 = (e / se) * g_aslots[b*NS + s];
            g_wc2[(b*NS + s)*NI + i] = wc2;
            wcsum += wc2;
        }
        g_wc2sum[b*NI + i] = wcsum;
        lg[i] = wcsum / g_aslots_sum[b];          // a_intents
    }
    __syncthreads();
    if (tid == 0) {
        float mx = lg[0]; int am = 0;
        for (int i = 1; i < NI; i++) if (lg[i] > mx) { mx = lg[i]; am = i; }
        g_maxidx[b] = am;
    }
}

// ============ Kernel Fa: column sums for USED (s,intent) pairs only ============
// colsum[s,i,k] = sum_j w_pose_si[s,i,j,k]; skip (s,i) no batch selected.
__global__ __launch_bounds__(512, 1) void kFa(const float* __restrict__ wps) {
    int blk = blockIdx.x;                  // [0, NS*NI)
    int s = blk / NI, i = blk % NI;
    bool used = false;
    #pragma unroll
    for (int b = 0; b < B; b++) used |= (g_maxidx[b] == i);
    if (!used) return;
    int k = threadIdx.x;                   // 512 threads == D columns
    const float* Wp = wps + (size_t)(s*NI + i)*D*D + k;
    float acc = 0.f;
    #pragma unroll 16
    for (int j = 0; j < D; j++) acc += Wp[(size_t)j*D];
    g_colsum[(size_t)(s*NI + i)*D + k] = acc;
}

// ============ Kernel G: intents epilogue (fixed s order, cls residual) ============
__global__ void kG(const float* __restrict__ cls, float* __restrict__ out) {
    int t = blockIdx.x * 256 + threadIdx.x;       // [0, B*D)
    int b = t >> 9, k = t & 511;
    int ii = g_maxidx[b];
    float sum = 0.f;
    #pragma unroll
    for (int s = 0; s < NS; s++) {
        float cs = g_colsum[(size_t)(s*NI + ii)*D + k];
        float u  = g_uslots[(size_t)(b*NS + s)*D + k];
        float wc2s = g_wc2[(b*NS + s)*NI + ii];
        sum += cs * u * wc2s;
    }
    out[B*L + t] = cls[t] + sum / g_wc2sum[b*NI + ii];
}

// ---------------- launch ----------------
extern "C" void kernel_launch(void* const* d_in, const int* in_sizes, int n_in,
                              void* d_out, int out_size) {
    const float* x     = (const float*)d_in[0];  // token_features (B,L,D)
    const float* cls   = (const float*)d_in[1];  // cls_token (B,D)
    const float* w_rws = (const float*)d_in[2];  // w_route_ws (L,NS,D)
    const float* w_pws = (const float*)d_in[3];  // w_pose_ws (L,NS,D,D)
    const float* w_rsi = (const float*)d_in[4];  // w_route_si (NS,NI,D)
    const float* w_psi = (const float*)d_in[5];  // w_pose_si (NS,NI,D,D)
    float* out = (float*)d_out;

    static bool attr_done = false;
    if (!attr_done) {
        cudaFuncSetAttribute(kC, cudaFuncAttributeMaxDynamicSharedMemorySize, KC_SMEM);
        attr_done = true;
    }

    kA<<<B*L, 128>>>(x, w_rws, out);
    kB<<<B, 32>>>();
    kB<<<B, 32>>>();              // duplicate (idempotent): keeps kC at launch idx 3 for ncu
    kC<<<NS*L, 256, KC_SMEM>>>(x, w_pws);
    kD<<<(B*NS*D)/256, 256>>>();
    kE<<<B, 256>>>(w_rsi);
    kFa<<<NS*NI, 512>>>(w_psi);
    kG<<<(B*D)/256, 256>>>(cls, out);
}